// round 1
// baseline (speedup 1.0000x reference)
#include <cuda_runtime.h>

// Problem constants (fixed by the reference)
#define Nn   1000
#define INF_ 32
#define Hh   128
#define Mm   128
#define DEGk 16
#define Pp   2
#define OUTn 10
#define MAXD (10 * Nn)                 // max dequeues (scan length)
#define NSMAX 64
#define CAP  (NSMAX + MAXD * DEGk)     // 160064

// Persistent device state (static allocation — no cudaMalloc allowed)
__device__ float g_feats[Nn * Hh];
__device__ float g_final[Nn * Hh];
__device__ float g_tact[Nn];
__device__ int   g_qn[CAP];
__device__ float g_qm[(long long)CAP * Mm];   // ~82 MB

// ---------------------------------------------------------------------------
// Kernel 1: encoder + state init + queue seed.  grid = Nn blocks x Hh threads
// ---------------------------------------------------------------------------
__global__ void k_init(const float* __restrict__ xa,
                       const float* __restrict__ fmsg,
                       const int*  nstart_p,
                       const float* __restrict__ enc_w,
                       const float* __restrict__ enc_b)
{
    int n = blockIdx.x, t = threadIdx.x;
    __shared__ float sx[INF_];
    if (t < INF_) sx[t] = xa[n * INF_ + t];
    __syncthreads();

    float acc = enc_b[t];
#pragma unroll
    for (int k = 0; k < INF_; k++) acc += sx[k] * enc_w[k * Hh + t];

    g_feats[n * Hh + t] = acc;
    g_final[n * Hh + t] = 0.0f;
    if (t == 0) g_tact[n] = 0.0f;

    int ns = nstart_p ? *nstart_p : NSMAX;
    if (n < ns) {
        if (t == 0) g_qn[n] = n;
        g_qm[(long long)n * Mm + t] = fmsg[n * Mm + t];
    }
}

// ---------------------------------------------------------------------------
// Kernel 2: sequential queue simulation. ONE block, 256 threads.
//   warp 0 ballot-scans ahead over halted entries (exact skip equivalence:
//   tact is monotone non-decreasing, so a "halted" verdict never changes).
//   Processing: two 256->128 fp32 matvecs, split k across 8 warps,
//   each lane accumulating a float4 of outputs (coalesced 512B weight loads).
// ---------------------------------------------------------------------------
__global__ void __launch_bounds__(256, 1) k_main(
    const int*  __restrict__ neighbors,
    const int*  nstart_p,
    const float* __restrict__ ns_w, const float* __restrict__ ns_b,
    const float* __restrict__ nm_w, const float* __restrict__ nm_b,
    const float* __restrict__ act_w, const float* __restrict__ act_b)
{
    __shared__ float xs[256];                 // [feats[node] | msg]
    __shared__ float ys[256];                 // [ns | msg]
    __shared__ __align__(16) float sred[8 * 128];
    __shared__ float s_actw[256];
    __shared__ float s_nsb[128], s_nmb[128];
    __shared__ float s_wact[8];
    __shared__ float s_na;
    __shared__ int   s_pos, s_node, s_found;

    const int t    = threadIdx.x;
    const int lane = t & 31;
    const int warp = t >> 5;

    s_actw[t] = act_w[t];
    if (t < 128) { s_nsb[t] = ns_b[t]; s_nmb[t] = nm_b[t]; }
    const float actb = act_b[0];

    int head = 0;
    int tail = nstart_p ? *nstart_p : NSMAX;
    __syncthreads();

    while (true) {
        int limit = (tail < MAXD) ? tail : MAXD;
        if (head >= limit) break;

        // ---- skip-scan (warp 0): find first entry with tact <= 1-1e-7 ----
        if (warp == 0) {
            int p = head + lane;
            while (true) {
                bool  valid = (p < limit);
                int   nd    = valid ? g_qn[p] : 0;
                float ta    = valid ? g_tact[nd] : 2.0f;
                unsigned ok = __ballot_sync(0xffffffffu,
                                            valid && (ta <= 1.0f - 1e-7f));
                if (ok) {
                    int first = __ffs((int)ok) - 1;
                    int fn    = __shfl_sync(0xffffffffu, nd, first);
                    if (lane == 0) {
                        s_pos   = (p - lane) + first;
                        s_node  = fn;
                        s_found = 1;
                    }
                    break;
                }
                unsigned vb = __ballot_sync(0xffffffffu, valid);
                if (vb != 0xffffffffu) {        // reached limit, none runnable
                    if (lane == 0) s_found = 0;
                    break;
                }
                p += 32;
            }
        }
        __syncthreads();
        if (!s_found) break;          // all remaining dequeues are no-ops

        const int pos  = s_pos;
        const int node = s_node;

        // ---- gather x = [feats[node], msg] ----
        float xv;
        if (t < 128) {
            xv = g_feats[node * Hh + t];
        } else {
            xv = g_qm[(long long)pos * Mm + (t - 128)];
            ys[t] = xv;               // msg half of nm input, fixed now
        }
        xs[t] = xv;
        __syncthreads();

        // ---- ACT gate partial (warp reduce) ----
        float pa = xv * s_actw[t];
#pragma unroll
        for (int o = 16; o; o >>= 1) pa += __shfl_xor_sync(0xffffffffu, pa, o);
        if (lane == 0) s_wact[warp] = pa;
        __syncthreads();

        // thread 0: finish ACT; all threads: ns matvec (k split across warps)
        if (t == 0) {
            float a = s_wact[0] + s_wact[1] + s_wact[2] + s_wact[3]
                    + s_wact[4] + s_wact[5] + s_wact[6] + s_wact[7] + actb;
            float cand = 1.0f / (1.0f + expf(-a));
            float ta   = g_tact[node];
            float na   = (ta + cand > 1.0f) ? (1.0f - ta) : cand;
            s_na = na;
            g_tact[node] = ta + na;
        }
        {
            const float4* W = (const float4*)ns_w;   // row k: 32 float4
            float4 acc = make_float4(0.f, 0.f, 0.f, 0.f);
            int kb = warp * 32;
#pragma unroll 8
            for (int kk = 0; kk < 32; kk++) {
                float  xk = xs[kb + kk];
                float4 w  = W[(kb + kk) * 32 + lane];
                acc.x += xk * w.x; acc.y += xk * w.y;
                acc.z += xk * w.z; acc.w += xk * w.w;
            }
            ((float4*)sred)[warp * 32 + lane] = acc;
        }
        __syncthreads();

        // ---- finalize ns, update feats/final ----
        if (t < 128) {
            float s = s_nsb[t];
#pragma unroll
            for (int j = 0; j < 8; j++) s += sred[j * 128 + t];
            float nsv = fmaxf(s, 0.0f);
            ys[t] = nsv;
            g_feats[node * Hh + t]  = nsv;
            g_final[node * Hh + t] += nsv * s_na;
        }
        __syncthreads();

        // ---- nm matvec over ys = [ns, msg] ----
        {
            const float4* W = (const float4*)nm_w;
            float4 acc = make_float4(0.f, 0.f, 0.f, 0.f);
            int kb = warp * 32;
#pragma unroll 8
            for (int kk = 0; kk < 32; kk++) {
                float  yk = ys[kb + kk];
                float4 w  = W[(kb + kk) * 32 + lane];
                acc.x += yk * w.x; acc.y += yk * w.y;
                acc.z += yk * w.z; acc.w += yk * w.w;
            }
            ((float4*)sred)[warp * 32 + lane] = acc;
        }
        __syncthreads();

        // ---- finalize nm, enqueue 16 neighbor messages ----
        if (t < 128) {
            float s = s_nmb[t];
#pragma unroll
            for (int j = 0; j < 8; j++) s += sred[j * 128 + t];
#pragma unroll
            for (int j = 0; j < DEGk; j++)
                g_qm[(long long)(tail + j) * Mm + t] = s;
        } else if (t < 128 + DEGk) {
            g_qn[tail + (t - 128)] = neighbors[node * DEGk + (t - 128)];
        }

        head = pos + 1;
        tail += DEGk;
        __syncthreads();   // queue writes visible to next scan
    }
}

// ---------------------------------------------------------------------------
// Kernel 3: readout.  g = sum_n final; logits = g . dec_w + dec_b; log_softmax
// ---------------------------------------------------------------------------
__global__ void k_readout(const float* __restrict__ dec_w,
                          const float* __restrict__ dec_b,
                          float* __restrict__ out)
{
    __shared__ float sg[Hh];
    __shared__ float sl[Pp * OUTn];
    int t = threadIdx.x;

    float acc = 0.0f;
#pragma unroll 4
    for (int n = 0; n < Nn; n++) acc += g_final[n * Hh + t];
    sg[t] = acc;
    __syncthreads();

    if (t < Pp * OUTn) {
        int p = t / OUTn, o = t - p * OUTn;
        float a = dec_b[t];
#pragma unroll 4
        for (int h = 0; h < Hh; h++)
            a += sg[h] * dec_w[(p * Hh + h) * OUTn + o];
        sl[t] = a;
    }
    __syncthreads();

    if (t < Pp) {
        float mx = -1e30f;
        for (int o = 0; o < OUTn; o++) mx = fmaxf(mx, sl[t * OUTn + o]);
        float s = 0.0f;
        for (int o = 0; o < OUTn; o++) s += expf(sl[t * OUTn + o] - mx);
        float lse = mx + logf(s);
        for (int o = 0; o < OUTn; o++)
            out[t * OUTn + o] = sl[t * OUTn + o] - lse;
    }
}

// ---------------------------------------------------------------------------
extern "C" void kernel_launch(void* const* d_in, const int* in_sizes, int n_in,
                              void* d_out, int out_size)
{
    // Input order per reference signature; tolerate num_starts being absent.
    int off = (n_in >= 14) ? 1 : 0;
    const float* xa        = (const float*)d_in[0];
    const float* fmsg      = (const float*)d_in[1];
    const int*   neighbors = (const int*)  d_in[2];
    const int*   nstart    = off ? (const int*)d_in[3] : nullptr;
    const float* enc_w = (const float*)d_in[3 + off];
    const float* enc_b = (const float*)d_in[4 + off];
    const float* ns_w  = (const float*)d_in[5 + off];
    const float* ns_b  = (const float*)d_in[6 + off];
    const float* nm_w  = (const float*)d_in[7 + off];
    const float* nm_b  = (const float*)d_in[8 + off];
    const float* act_w = (const float*)d_in[9 + off];
    const float* act_b = (const float*)d_in[10 + off];
    const float* dec_w = (const float*)d_in[11 + off];
    const float* dec_b = (const float*)d_in[12 + off];

    k_init<<<Nn, Hh>>>(xa, fmsg, nstart, enc_w, enc_b);
    k_main<<<1, 256>>>(neighbors, nstart, ns_w, ns_b, nm_w, nm_b, act_w, act_b);
    k_readout<<<1, Hh>>>(dec_w, dec_b, (float*)d_out);
}

// round 2
// speedup vs baseline: 1.7086x; 1.7086x over previous
#include <cuda_runtime.h>

// Problem constants (fixed by the reference)
#define Nn    1000
#define INF_  32
#define Hh    128
#define Mm    128
#define DEGk  16
#define Pp    2
#define OUTn  10
#define MAXD  (10 * Nn)                 // dequeue budget (scan length)
#define NSMAX 64
#define CAP   (NSMAX + MAXD * DEGk)     // 160064 queue slots
#define MAXMSG (NSMAX + MAXD)           // distinct messages ever created

// Persistent device state (static allocation — no cudaMalloc allowed)
__device__ float g_feats[Nn * Hh];
__device__ float g_final[Nn * Hh];
__device__ float g_tact[Nn];
__device__ int   g_qn[CAP];
__device__ int   g_qmid[CAP];
__device__ float g_msgs[(size_t)MAXMSG * Mm];   // dedup'd message store (~5.2 MB)

// ---------------------------------------------------------------------------
// Kernel 1: encoder + state init + queue seed.  grid = Nn blocks x 128 threads
// ---------------------------------------------------------------------------
__global__ void k_init(const float* __restrict__ xa,
                       const float* __restrict__ fmsg,
                       const int*  nstart_p,
                       const float* __restrict__ enc_w,
                       const float* __restrict__ enc_b)
{
    int n = blockIdx.x, t = threadIdx.x;
    __shared__ float sx[INF_];
    if (t < INF_) sx[t] = xa[n * INF_ + t];
    __syncthreads();

    float acc = enc_b[t];
#pragma unroll
    for (int k = 0; k < INF_; k++) acc += sx[k] * enc_w[k * Hh + t];

    g_feats[n * Hh + t] = acc;
    g_final[n * Hh + t] = 0.0f;
    if (t == 0) g_tact[n] = 0.0f;

    int ns = nstart_p ? *nstart_p : NSMAX;
    if (n < ns) {
        if (t == 0) { g_qn[n] = n; g_qmid[n] = n; }
        g_msgs[(size_t)n * Mm + t] = fmsg[n * Mm + t];
    }
}

// ---------------------------------------------------------------------------
// Kernel 2: sequential queue simulation. ONE block, 256 threads.
//  * warp-0 ballot skip-scan over halted entries (exact: tact monotone).
//  * message dedup: 16 siblings share one stored message (mid).
//  * msg-half partials of ns/nm/act matvecs cached per mid.
//  * feats-half weights (128 KB) resident in shared memory.
// ---------------------------------------------------------------------------
__global__ void __launch_bounds__(256, 1) k_main(
    const int*  __restrict__ neighbors,
    const int*  nstart_p,
    const float* __restrict__ ns_w, const float* __restrict__ ns_b,
    const float* __restrict__ nm_w, const float* __restrict__ nm_b,
    const float* __restrict__ act_w, const float* __restrict__ act_b)
{
    extern __shared__ __align__(16) float dyn[];
    float4* s_nsw4 = (float4*)dyn;                  // ns_w rows 0..127 (64 KB)
    float4* s_nmw4 = (float4*)(dyn + 128 * 128);    // nm_w rows 0..127 (64 KB)

    __shared__ float xs[128];                       // feats[node]
    __shared__ float ys[128];                       // ns output
    __shared__ float s_msg[128];                    // current message (miss path)
    __shared__ float s_nsmsg[128], s_nmmsg[128];    // cached msg-half partials
    __shared__ __align__(16) float sredA[8 * 128];
    __shared__ __align__(16) float sredB[8 * 128];
    __shared__ float s_actw[256];
    __shared__ float s_nsb[128], s_nmb[128];
    __shared__ float s_wact[8];
    __shared__ float s_actmsg, s_na, s_ta;
    __shared__ int   s_pos, s_node, s_mid, s_found, s_nb[DEGk];

    const int t    = threadIdx.x;
    const int lane = t & 31;
    const int warp = t >> 5;

    s_actw[t] = act_w[t];
    if (t < 128) { s_nsb[t] = ns_b[t]; s_nmb[t] = nm_b[t]; }
    const float actb = act_b[0];

    // Preload feats-half weights into shared (4096 float4 each)
    {
        const float4* g_ns4 = (const float4*)ns_w;
        const float4* g_nm4 = (const float4*)nm_w;
        for (int i = t; i < 128 * 32; i += 256) {
            s_nsw4[i] = g_ns4[i];
            s_nmw4[i] = g_nm4[i];
        }
    }

    int head = 0;
    int tail = nstart_p ? *nstart_p : NSMAX;
    int nproc = 0;
    int last_mid = -1;
    __syncthreads();

    while (true) {
        int limit = (tail < MAXD) ? tail : MAXD;    // dequeue budget
        if (head >= limit) break;

        // ---- skip-scan (warp 0): first entry with tact <= 1-1e-7 ----
        if (warp == 0) {
            int p = head + lane;
            while (true) {
                bool  valid = (p < limit);
                int   nd    = valid ? g_qn[p] : 0;
                float ta    = valid ? g_tact[nd] : 2.0f;
                unsigned ok = __ballot_sync(0xffffffffu,
                                            valid && (ta <= 1.0f - 1e-7f));
                if (ok) {
                    int first = __ffs((int)ok) - 1;
                    int fn = __shfl_sync(0xffffffffu, nd, first);
                    float fta = __shfl_sync(0xffffffffu, ta, first);
                    if (lane == 0) {
                        int pos = (p - lane) + first;
                        s_pos = pos; s_node = fn; s_ta = fta;
                        s_mid = g_qmid[pos];
                        s_found = 1;
                    }
                    break;
                }
                unsigned vb = __ballot_sync(0xffffffffu, valid);
                if (vb != 0xffffffffu) { if (lane == 0) s_found = 0; break; }
                p += 32;
            }
        }
        __syncthreads();
        if (!s_found) break;          // all remaining dequeues are no-ops

        const int pos  = s_pos;
        const int node = s_node;
        const int mid  = s_mid;

        // ---- miss path: compute msg-half partials for this mid ----
        if (mid != last_mid) {
            if (t < 128) s_msg[t] = g_msgs[(size_t)mid * Mm + t];
            __syncthreads();

            {   // warp w handles msg rows k = w*16 .. w*16+15 (global rows 128+k)
                const float4* g_ns4 = (const float4*)ns_w;
                const float4* g_nm4 = (const float4*)nm_w;
                float4 a = make_float4(0.f,0.f,0.f,0.f);
                float4 b = make_float4(0.f,0.f,0.f,0.f);
                int kb = warp * 16;
#pragma unroll 8
                for (int kk = 0; kk < 16; kk++) {
                    float  mk = s_msg[kb + kk];
                    float4 wa = g_ns4[(128 + kb + kk) * 32 + lane];
                    float4 wb = g_nm4[(128 + kb + kk) * 32 + lane];
                    a.x += mk * wa.x; a.y += mk * wa.y;
                    a.z += mk * wa.z; a.w += mk * wa.w;
                    b.x += mk * wb.x; b.y += mk * wb.y;
                    b.z += mk * wb.z; b.w += mk * wb.w;
                }
                ((float4*)sredA)[warp * 32 + lane] = a;
                ((float4*)sredB)[warp * 32 + lane] = b;
            }
            // act msg-half partial (warps 0-3)
            {
                float pa = (t < 128) ? s_msg[t] * s_actw[128 + t] : 0.0f;
#pragma unroll
                for (int o = 16; o; o >>= 1)
                    pa += __shfl_xor_sync(0xffffffffu, pa, o);
                if (lane == 0 && warp < 4) s_wact[warp] = pa;
            }
            __syncthreads();
            if (t < 128) {
                float sa = 0.f, sb = 0.f;
#pragma unroll
                for (int j = 0; j < 8; j++) {
                    sa += sredA[j * 128 + t];
                    sb += sredB[j * 128 + t];
                }
                s_nsmsg[t] = sa; s_nmmsg[t] = sb;
            }
            if (t == 0)
                s_actmsg = s_wact[0] + s_wact[1] + s_wact[2] + s_wact[3];
            __syncthreads();
            last_mid = mid;
        }

        // ---- gather feats + act feats-half partial; prefetch neighbors ----
        {
            float pa = 0.0f;
            if (t < 128) {
                float xv = g_feats[node * Hh + t];
                xs[t] = xv;
                pa = xv * s_actw[t];
            } else if (t < 128 + DEGk) {
                s_nb[t - 128] = neighbors[node * DEGk + (t - 128)];
            }
#pragma unroll
            for (int o = 16; o; o >>= 1)
                pa += __shfl_xor_sync(0xffffffffu, pa, o);
            if (lane == 0 && warp < 4) s_wact[warp] = pa;
        }
        __syncthreads();

        // thread 0: finish ACT; all: ns feats-half matvec
        if (t == 0) {
            float a = s_wact[0] + s_wact[1] + s_wact[2] + s_wact[3]
                    + s_actmsg + actb;
            float cand = 1.0f / (1.0f + expf(-a));
            float ta = s_ta;
            float na = (ta + cand > 1.0f) ? (1.0f - ta) : cand;
            s_na = na;
            g_tact[node] = ta + na;
        }
        {
            float4 acc = make_float4(0.f,0.f,0.f,0.f);
            int kb = warp * 16;
#pragma unroll 8
            for (int kk = 0; kk < 16; kk++) {
                float  xk = xs[kb + kk];
                float4 w  = s_nsw4[(kb + kk) * 32 + lane];
                acc.x += xk * w.x; acc.y += xk * w.y;
                acc.z += xk * w.z; acc.w += xk * w.w;
            }
            ((float4*)sredA)[warp * 32 + lane] = acc;
        }
        __syncthreads();

        // ---- finalize ns, update feats/final ----
        if (t < 128) {
            float s = s_nsb[t] + s_nsmsg[t];
#pragma unroll
            for (int j = 0; j < 8; j++) s += sredA[j * 128 + t];
            float nsv = fmaxf(s, 0.0f);
            ys[t] = nsv;
            g_feats[node * Hh + t]  = nsv;
            g_final[node * Hh + t] += nsv * s_na;
        }
        __syncthreads();

        // ---- nm ns-half matvec over ys ----
        {
            float4 acc = make_float4(0.f,0.f,0.f,0.f);
            int kb = warp * 16;
#pragma unroll 8
            for (int kk = 0; kk < 16; kk++) {
                float  yk = ys[kb + kk];
                float4 w  = s_nmw4[(kb + kk) * 32 + lane];
                acc.x += yk * w.x; acc.y += yk * w.y;
                acc.z += yk * w.z; acc.w += yk * w.w;
            }
            ((float4*)sredB)[warp * 32 + lane] = acc;
        }
        __syncthreads();

        // ---- finalize nm, store message ONCE, enqueue 16 (node,mid) pairs ----
        const int newmid = NSMAX + nproc;
        if (t < 128) {
            float s = s_nmb[t] + s_nmmsg[t];
#pragma unroll
            for (int j = 0; j < 8; j++) s += sredB[j * 128 + t];
            g_msgs[(size_t)newmid * Mm + t] = s;
        } else if (t < 128 + DEGk) {
            int j = t - 128;
            g_qn[tail + j]   = s_nb[j];
            g_qmid[tail + j] = newmid;
        }

        head = pos + 1;
        tail += DEGk;
        nproc += 1;
        __syncthreads();   // queue/tact/msg writes visible to next scan
    }
}

// ---------------------------------------------------------------------------
// Kernel 3: readout.  g = sum_n final; logits = g . dec_w + dec_b; log_softmax
// ---------------------------------------------------------------------------
__global__ void k_readout(const float* __restrict__ dec_w,
                          const float* __restrict__ dec_b,
                          float* __restrict__ out)
{
    __shared__ float sg[Hh];
    __shared__ float sl[Pp * OUTn];
    int t = threadIdx.x;

    float acc = 0.0f;
#pragma unroll 4
    for (int n = 0; n < Nn; n++) acc += g_final[n * Hh + t];
    sg[t] = acc;
    __syncthreads();

    if (t < Pp * OUTn) {
        int p = t / OUTn, o = t - p * OUTn;
        float a = dec_b[t];
#pragma unroll 4
        for (int h = 0; h < Hh; h++)
            a += sg[h] * dec_w[(p * Hh + h) * OUTn + o];
        sl[t] = a;
    }
    __syncthreads();

    if (t < Pp) {
        float mx = -1e30f;
        for (int o = 0; o < OUTn; o++) mx = fmaxf(mx, sl[t * OUTn + o]);
        float s = 0.0f;
        for (int o = 0; o < OUTn; o++) s += expf(sl[t * OUTn + o] - mx);
        float lse = mx + logf(s);
        for (int o = 0; o < OUTn; o++)
            out[t * OUTn + o] = sl[t * OUTn + o] - lse;
    }
}

// ---------------------------------------------------------------------------
extern "C" void kernel_launch(void* const* d_in, const int* in_sizes, int n_in,
                              void* d_out, int out_size)
{
    int off = (n_in >= 14) ? 1 : 0;
    const float* xa        = (const float*)d_in[0];
    const float* fmsg      = (const float*)d_in[1];
    const int*   neighbors = (const int*)  d_in[2];
    const int*   nstart    = off ? (const int*)d_in[3] : nullptr;
    const float* enc_w = (const float*)d_in[3 + off];
    const float* enc_b = (const float*)d_in[4 + off];
    const float* ns_w  = (const float*)d_in[5 + off];
    const float* ns_b  = (const float*)d_in[6 + off];
    const float* nm_w  = (const float*)d_in[7 + off];
    const float* nm_b  = (const float*)d_in[8 + off];
    const float* act_w = (const float*)d_in[9 + off];
    const float* act_b = (const float*)d_in[10 + off];
    const float* dec_w = (const float*)d_in[11 + off];
    const float* dec_b = (const float*)d_in[12 + off];

    static const size_t DYN = 2 * 128 * 128 * sizeof(float);   // 128 KB
    cudaFuncSetAttribute(k_main, cudaFuncAttributeMaxDynamicSharedMemorySize,
                         (int)DYN);

    k_init<<<Nn, Hh>>>(xa, fmsg, nstart, enc_w, enc_b);
    k_main<<<1, 256, DYN>>>(neighbors, nstart, ns_w, ns_b, nm_w, nm_b,
                            act_w, act_b);
    k_readout<<<1, Hh>>>(dec_w, dec_b, (float*)d_out);
}

// round 3
// speedup vs baseline: 2.0634x; 1.2076x over previous
#include <cuda_runtime.h>

// Problem constants (fixed by the reference)
#define Nn    1000
#define INF_  32
#define Hh    128
#define Mm    128
#define DEGk  16
#define Pp    2
#define OUTn  10
#define MAXD  (10 * Nn)                 // dequeue budget (scan length) = queue slots ever read
#define NSMAX 64
#define MAXMSG (NSMAX + MAXD)           // distinct messages ever created

// Persistent device state (static allocation — no cudaMalloc allowed)
__device__ float g_feats[Nn * Hh];
__device__ float g_final[Nn * Hh];
__device__ float g_msgs[(size_t)MAXMSG * Mm];   // dedup'd message store (~5.2 MB)

// ---------------------------------------------------------------------------
// Kernel 1: encoder + state init + seed message store. grid = Nn x 128
// ---------------------------------------------------------------------------
__global__ void k_init(const float* __restrict__ xa,
                       const float* __restrict__ fmsg,
                       const int*  nstart_p,
                       const float* __restrict__ enc_w,
                       const float* __restrict__ enc_b)
{
    int n = blockIdx.x, t = threadIdx.x;
    __shared__ float sx[INF_];
    if (t < INF_) sx[t] = xa[n * INF_ + t];
    __syncthreads();

    float acc = enc_b[t];
#pragma unroll
    for (int k = 0; k < INF_; k++) acc += sx[k] * enc_w[k * Hh + t];

    g_feats[n * Hh + t] = acc;
    g_final[n * Hh + t] = 0.0f;

    int ns = nstart_p ? *nstart_p : NSMAX;
    if (n < ns) g_msgs[(size_t)n * Mm + t] = fmsg[n * Mm + t];
}

// ---------------------------------------------------------------------------
// Kernel 2: sequential queue simulation. ONE block, 256 threads.
//  * queue (packed mid<<10|node, first MAXD slots only) + tact in SMEM
//  * all warps scan redundantly (no publish barrier)
//  * message dedup + per-mid cached msg-half partials
//  * feats-half weights (128 KB) resident in SMEM
//  * ACT finalize computed redundantly by all threads
// ---------------------------------------------------------------------------
__global__ void __launch_bounds__(256, 1) k_main(
    const int*  __restrict__ neighbors,
    const int*  nstart_p,
    const float* __restrict__ ns_w, const float* __restrict__ ns_b,
    const float* __restrict__ nm_w, const float* __restrict__ nm_b,
    const float* __restrict__ act_w, const float* __restrict__ act_b)
{
    extern __shared__ __align__(16) float dyn[];
    float4* s_nsw4  = (float4*)dyn;                     // ns_w rows 0..127 (64 KB)
    float4* s_nmw4  = (float4*)(dyn + 128 * 128);       // nm_w rows 0..127 (64 KB)
    int*    s_qpack = (int*)(dyn + 2 * 128 * 128);      // packed queue (40 KB)

    __shared__ float s_tact[Nn];                        // 4 KB
    __shared__ float xs[128];                           // feats[node]
    __shared__ float ys[128];                           // ns output
    __shared__ float s_msg[128];
    __shared__ float s_nsmsg[128], s_nmmsg[128];        // cached msg-half partials
    __shared__ __align__(16) float sredA[8 * 128];
    __shared__ __align__(16) float sredB[8 * 128];
    __shared__ float s_actw[256];
    __shared__ float s_nsb[128], s_nmb[128];
    __shared__ float s_wact[4];                         // feats-half act partials
    __shared__ float s_wactm[4];                        // msg-half act partials
    __shared__ float s_actmsg;

    const int t    = threadIdx.x;
    const int lane = t & 31;
    const int warp = t >> 5;
    const unsigned FULL = 0xffffffffu;

    s_actw[t] = act_w[t];
    if (t < 128) { s_nsb[t] = ns_b[t]; s_nmb[t] = nm_b[t]; }
    const float actb = act_b[0];

    for (int i = t; i < Nn; i += 256) s_tact[i] = 0.0f;

    const int ns0 = nstart_p ? *nstart_p : NSMAX;
    for (int i = t; i < ns0; i += 256) s_qpack[i] = (i << 10) | i;   // mid=i, node=i

    // Preload feats-half weights into shared (4096 float4 each)
    {
        const float4* g_ns4 = (const float4*)ns_w;
        const float4* g_nm4 = (const float4*)nm_w;
        for (int i = t; i < 128 * 32; i += 256) {
            s_nsw4[i] = g_ns4[i];
            s_nmw4[i] = g_nm4[i];
        }
    }

    int head = 0;
    int tail = ns0;
    int nproc = 0;
    int last_mid = -1;
    __syncthreads();

    while (true) {
        int limit = (tail < MAXD) ? tail : MAXD;    // dequeue budget
        if (head >= limit) break;

        // ---- skip-scan: ALL warps scan SMEM redundantly; result in regs ----
        int pos, node, mid; float ta; int found = 1;
        {
            int p = head + lane;
            while (true) {
                bool  valid = (p < limit);
                int   pk    = valid ? s_qpack[p] : 0;
                int   nd    = pk & 1023;
                float tv    = valid ? s_tact[nd] : 2.0f;
                unsigned ok = __ballot_sync(FULL, valid && (tv <= 1.0f - 1e-7f));
                if (ok) {
                    int f = __ffs((int)ok) - 1;
                    pos  = (p - lane) + f;
                    node = __shfl_sync(FULL, nd, f);
                    mid  = __shfl_sync(FULL, pk, f) >> 10;
                    ta   = __shfl_sync(FULL, tv, f);
                    break;
                }
                if (__ballot_sync(FULL, valid) != FULL) { found = 0; break; }
                p += 32;
            }
        }
        if (!found) break;            // all remaining dequeues are no-ops

        // ---- miss path: compute msg-half partials for this mid ----
        if (mid != last_mid) {
            float mv = 0.0f;
            if (t < 128) {
                mv = g_msgs[(size_t)mid * Mm + t];
                s_msg[t] = mv;
            }
            {   // act msg-half partial (warps 0-3, from register)
                float pa = mv * s_actw[128 + (t & 127)];
                if (t >= 128) pa = 0.0f;
#pragma unroll
                for (int o = 16; o; o >>= 1)
                    pa += __shfl_xor_sync(FULL, pa, o);
                if (lane == 0 && warp < 4) s_wactm[warp] = pa;
            }
            __syncthreads();
            {   // warp w: msg rows kb..kb+15 (global rows 128+), from L2
                const float4* g_ns4 = (const float4*)ns_w;
                const float4* g_nm4 = (const float4*)nm_w;
                float4 a = make_float4(0.f,0.f,0.f,0.f);
                float4 b = make_float4(0.f,0.f,0.f,0.f);
                int kb = warp * 16;
#pragma unroll 8
                for (int kk = 0; kk < 16; kk++) {
                    float  mk = s_msg[kb + kk];
                    float4 wa = g_ns4[(128 + kb + kk) * 32 + lane];
                    float4 wb = g_nm4[(128 + kb + kk) * 32 + lane];
                    a.x += mk * wa.x; a.y += mk * wa.y;
                    a.z += mk * wa.z; a.w += mk * wa.w;
                    b.x += mk * wb.x; b.y += mk * wb.y;
                    b.z += mk * wb.z; b.w += mk * wb.w;
                }
                ((float4*)sredA)[warp * 32 + lane] = a;
                ((float4*)sredB)[warp * 32 + lane] = b;
            }
            __syncthreads();
            if (t < 128) {
                float sa = 0.f, sb = 0.f;
#pragma unroll
                for (int j = 0; j < 8; j++) {
                    sa += sredA[j * 128 + t];
                    sb += sredB[j * 128 + t];
                }
                s_nsmsg[t] = sa; s_nmmsg[t] = sb;
            }
            if (t == 0)
                s_actmsg = s_wactm[0] + s_wactm[1] + s_wactm[2] + s_wactm[3];
            __syncthreads();
            last_mid = mid;
        }

        // ---- gather feats (+ act feats-half partial); warp4: neighbors ----
        int mynb = 0;
        {
            float pa = 0.0f;
            if (t < 128) {
                float xv = g_feats[node * Hh + t];
                xs[t] = xv;
                pa = xv * s_actw[t];
            } else if (warp == 4 && lane < DEGk) {
                mynb = neighbors[node * DEGk + lane];
            }
#pragma unroll
            for (int o = 16; o; o >>= 1)
                pa += __shfl_xor_sync(FULL, pa, o);
            if (lane == 0 && warp < 4) s_wact[warp] = pa;
        }
        __syncthreads();

        // ---- ACT finalize (all threads, redundantly) ----
        float na;
        {
            float a = s_wact[0] + s_wact[1] + s_wact[2] + s_wact[3]
                    + s_actmsg + actb;
            float cand = 1.0f / (1.0f + expf(-a));
            na = (ta + cand > 1.0f) ? (1.0f - ta) : cand;
        }
        if (t == 0) s_tact[node] = ta + na;

        // ---- ns feats-half matvec (SMEM weights) ----
        {
            float4 acc = make_float4(0.f,0.f,0.f,0.f);
            int kb = warp * 16;
#pragma unroll 8
            for (int kk = 0; kk < 16; kk++) {
                float  xk = xs[kb + kk];
                float4 w  = s_nsw4[(kb + kk) * 32 + lane];
                acc.x += xk * w.x; acc.y += xk * w.y;
                acc.z += xk * w.z; acc.w += xk * w.w;
            }
            ((float4*)sredA)[warp * 32 + lane] = acc;
        }
        __syncthreads();

        // ---- finalize ns, update feats/final ----
        if (t < 128) {
            float s = s_nsb[t] + s_nsmsg[t];
#pragma unroll
            for (int j = 0; j < 8; j++) s += sredA[j * 128 + t];
            float nsv = fmaxf(s, 0.0f);
            ys[t] = nsv;
            g_feats[node * Hh + t]  = nsv;
            g_final[node * Hh + t] += nsv * na;
        }
        __syncthreads();

        // ---- nm ns-half matvec (SMEM weights) ----
        {
            float4 acc = make_float4(0.f,0.f,0.f,0.f);
            int kb = warp * 16;
#pragma unroll 8
            for (int kk = 0; kk < 16; kk++) {
                float  yk = ys[kb + kk];
                float4 w  = s_nmw4[(kb + kk) * 32 + lane];
                acc.x += yk * w.x; acc.y += yk * w.y;
                acc.z += yk * w.z; acc.w += yk * w.w;
            }
            ((float4*)sredB)[warp * 32 + lane] = acc;
        }
        __syncthreads();

        // ---- finalize nm: store message once; enqueue 16 (node,mid) ----
        const int newmid = NSMAX + nproc;
        if (t < 128) {
            float s = s_nmb[t] + s_nmmsg[t];
#pragma unroll
            for (int j = 0; j < 8; j++) s += sredB[j * 128 + t];
            g_msgs[(size_t)newmid * Mm + t] = s;
        } else if (warp == 4 && lane < DEGk) {
            int slot = tail + lane;
            if (slot < MAXD) s_qpack[slot] = (newmid << 10) | mynb;
        }

        head = pos + 1;
        tail += DEGk;
        nproc += 1;
        last_mid = mid;
        __syncthreads();   // queue/tact/msg writes visible to next scan
    }
}

// ---------------------------------------------------------------------------
// Kernel 3: readout.  g = sum_n final; logits = g . dec_w + dec_b; log_softmax
// ---------------------------------------------------------------------------
__global__ void k_readout(const float* __restrict__ dec_w,
                          const float* __restrict__ dec_b,
                          float* __restrict__ out)
{
    __shared__ float sg[Hh];
    __shared__ float sl[Pp * OUTn];
    int t = threadIdx.x;

    float acc = 0.0f;
#pragma unroll 4
    for (int n = 0; n < Nn; n++) acc += g_final[n * Hh + t];
    sg[t] = acc;
    __syncthreads();

    if (t < Pp * OUTn) {
        int p = t / OUTn, o = t - p * OUTn;
        float a = dec_b[t];
#pragma unroll 4
        for (int h = 0; h < Hh; h++)
            a += sg[h] * dec_w[(p * Hh + h) * OUTn + o];
        sl[t] = a;
    }
    __syncthreads();

    if (t < Pp) {
        float mx = -1e30f;
        for (int o = 0; o < OUTn; o++) mx = fmaxf(mx, sl[t * OUTn + o]);
        float s = 0.0f;
        for (int o = 0; o < OUTn; o++) s += expf(sl[t * OUTn + o] - mx);
        float lse = mx + logf(s);
        for (int o = 0; o < OUTn; o++)
            out[t * OUTn + o] = sl[t * OUTn + o] - lse;
    }
}

// ---------------------------------------------------------------------------
extern "C" void kernel_launch(void* const* d_in, const int* in_sizes, int n_in,
                              void* d_out, int out_size)
{
    int off = (n_in >= 14) ? 1 : 0;
    const float* xa        = (const float*)d_in[0];
    const float* fmsg      = (const float*)d_in[1];
    const int*   neighbors = (const int*)  d_in[2];
    const int*   nstart    = off ? (const int*)d_in[3] : nullptr;
    const float* enc_w = (const float*)d_in[3 + off];
    const float* enc_b = (const float*)d_in[4 + off];
    const float* ns_w  = (const float*)d_in[5 + off];
    const float* ns_b  = (const float*)d_in[6 + off];
    const float* nm_w  = (const float*)d_in[7 + off];
    const float* nm_b  = (const float*)d_in[8 + off];
    const float* act_w = (const float*)d_in[9 + off];
    const float* act_b = (const float*)d_in[10 + off];
    const float* dec_w = (const float*)d_in[11 + off];
    const float* dec_b = (const float*)d_in[12 + off];

    // dynamic smem: 128 KB weights + 40 KB packed queue
    static const size_t DYN = 2 * 128 * 128 * sizeof(float) + MAXD * sizeof(int);
    cudaFuncSetAttribute(k_main, cudaFuncAttributeMaxDynamicSharedMemorySize,
                         (int)DYN);

    k_init<<<Nn, Hh>>>(xa, fmsg, nstart, enc_w, enc_b);
    k_main<<<1, 256, DYN>>>(neighbors, nstart, ns_w, ns_b, nm_w, nm_b,
                            act_w, act_b);
    k_readout<<<1, Hh>>>(dec_w, dec_b, (float*)d_out);
}

// round 4
// speedup vs baseline: 2.1589x; 1.0463x over previous
#include <cuda_runtime.h>

// Problem constants (fixed by the reference)
#define Nn    1000
#define INF_  32
#define Hh    128
#define Mm    128
#define DEGk  16
#define Pp    2
#define OUTn  10
#define MAXD  (10 * Nn)                 // dequeue budget = queue slots ever read
#define NSMAX 64
#define MAXMSG (NSMAX + MAXD)           // distinct messages ever created

// Persistent device state (static allocation — no cudaMalloc allowed)
__device__ float g_feats[Nn * Hh];
__device__ float g_final[Nn * Hh];
__device__ float g_msgs[(size_t)MAXMSG * Mm];   // dedup'd message store (~5.2 MB)

// ---- packed f32x2 helpers (sm_103a) ---------------------------------------
__device__ __forceinline__ unsigned long long fma2(unsigned long long a,
                                                   unsigned long long b,
                                                   unsigned long long c)
{
    unsigned long long d;
    asm("fma.rn.f32x2 %0, %1, %2, %3;" : "=l"(d) : "l"(a), "l"(b), "l"(c));
    return d;
}
__device__ __forceinline__ unsigned long long pack2(float lo, float hi)
{
    unsigned long long d;
    asm("mov.b64 %0, {%1, %2};" : "=l"(d) : "f"(lo), "f"(hi));
    return d;
}
__device__ __forceinline__ void unpack2(unsigned long long v, float& lo, float& hi)
{
    asm("mov.b64 {%0, %1}, %2;" : "=f"(lo), "=f"(hi) : "l"(v));
}

// ---------------------------------------------------------------------------
// Kernel 1: encoder + state init + seed message store. grid = Nn x 128
// ---------------------------------------------------------------------------
__global__ void k_init(const float* __restrict__ xa,
                       const float* __restrict__ fmsg,
                       const int*  nstart_p,
                       const float* __restrict__ enc_w,
                       const float* __restrict__ enc_b)
{
    int n = blockIdx.x, t = threadIdx.x;
    __shared__ float sx[INF_];
    if (t < INF_) sx[t] = xa[n * INF_ + t];
    __syncthreads();

    float acc = enc_b[t];
#pragma unroll
    for (int k = 0; k < INF_; k++) acc += sx[k] * enc_w[k * Hh + t];

    g_feats[n * Hh + t] = acc;
    g_final[n * Hh + t] = 0.0f;

    int ns = nstart_p ? *nstart_p : NSMAX;
    if (n < ns) g_msgs[(size_t)n * Mm + t] = fmsg[n * Mm + t];
}

// ---------------------------------------------------------------------------
// Kernel 2: sequential queue simulation. ONE block, 512 threads (16 warps).
//  * queue (packed mid<<10|node) + tact in SMEM; all warps scan redundantly
//  * hit-path weights (feats/ns halves of ns_w,nm_w) REGISTER-resident:
//      warp w owns outputs [w*8, w*8+8); lane: out o=w*8+(l&7), k-chunk c=l>>3
//      k packed in pairs -> fma.rn.f32x2; warp-local shfl reduce (no smem red)
//  * message dedup + per-mid cached msg-half partials (miss: L2 streamed,
//      two matrices processed concurrently by warp groups 0-7 / 8-15)
// ---------------------------------------------------------------------------
__global__ void __launch_bounds__(512, 1) k_main(
    const int*  __restrict__ neighbors,
    const int*  nstart_p,
    const float* __restrict__ ns_w, const float* __restrict__ ns_b,
    const float* __restrict__ nm_w, const float* __restrict__ nm_b,
    const float* __restrict__ act_w, const float* __restrict__ act_b)
{
    extern __shared__ __align__(16) int s_qpack[];      // packed queue (40 KB)

    __shared__ float s_tact[Nn];                        // 4 KB
    __shared__ __align__(16) float xs[128];             // feats[node]
    __shared__ __align__(16) float ys[128];             // ns output (relu)
    __shared__ float s_msg[128];
    __shared__ float s_nsmsg[128], s_nmmsg[128];        // cached msg-half partials
    __shared__ __align__(16) float sredA[8 * 128];      // miss-path partials (ns)
    __shared__ __align__(16) float sredB[8 * 128];      // miss-path partials (nm)
    __shared__ float s_actw[256];
    __shared__ float s_nsb[128], s_nmb[128];
    __shared__ float s_wact[4];                         // feats-half act partials
    __shared__ float s_wactm[4];                        // msg-half act partials
    __shared__ float s_actmsg;

    const int t    = threadIdx.x;
    const int lane = t & 31;
    const int warp = t >> 5;
    const unsigned FULL = 0xffffffffu;

    if (t < 256) s_actw[t] = act_w[t];
    if (t < 128) { s_nsb[t] = ns_b[t]; s_nmb[t] = nm_b[t]; }
    const float actb = act_b[0];

    for (int i = t; i < Nn; i += 512) s_tact[i] = 0.0f;

    const int ns0 = nstart_p ? *nstart_p : NSMAX;
    for (int i = t; i < ns0; i += 512) s_qpack[i] = (i << 10) | i;  // mid=i,node=i

    // ---- load hit-path weights into registers (k-pair packed) ----
    const int o = (warp << 3) + (lane & 7);     // output column owned
    const int c = lane >> 3;                    // k-chunk (0..3), k in [32c,32c+32)
    unsigned long long wA[16], wB[16];
#pragma unroll
    for (int kk = 0; kk < 16; kk++) {
        int k = c * 32 + 2 * kk;
        wA[kk] = pack2(ns_w[k * Hh + o], ns_w[(k + 1) * Hh + o]);
        wB[kk] = pack2(nm_w[k * Hh + o], nm_w[(k + 1) * Hh + o]);
    }

    int head = 0;
    int tail = ns0;
    int nproc = 0;
    int last_mid = -1;
    __syncthreads();

    while (true) {
        int limit = (tail < MAXD) ? tail : MAXD;    // dequeue budget
        if (head >= limit) break;

        // ---- skip-scan: all warps scan SMEM redundantly; result in regs ----
        int pos, node, mid; float ta; int found = 1;
        {
            int p = head + lane;
            while (true) {
                bool  valid = (p < limit);
                int   pk    = valid ? s_qpack[p] : 0;
                int   nd    = pk & 1023;
                float tv    = valid ? s_tact[nd] : 2.0f;
                unsigned ok = __ballot_sync(FULL, valid && (tv <= 1.0f - 1e-7f));
                if (ok) {
                    int f = __ffs((int)ok) - 1;
                    pos  = (p - lane) + f;
                    node = __shfl_sync(FULL, nd, f);
                    mid  = __shfl_sync(FULL, pk, f) >> 10;
                    ta   = __shfl_sync(FULL, tv, f);
                    break;
                }
                if (__ballot_sync(FULL, valid) != FULL) { found = 0; break; }
                p += 32;
            }
        }
        if (!found) break;            // all remaining dequeues are no-ops

        // ---- miss path: compute msg-half partials for this mid ----
        if (mid != last_mid) {
            float mv = 0.0f;
            if (t < 128) {
                mv = g_msgs[(size_t)mid * Mm + t];
                s_msg[t] = mv;
            }
            if (warp < 4) {           // act msg-half partial
                float pa = mv * s_actw[128 + (t & 127)];
#pragma unroll
                for (int oo = 16; oo; oo >>= 1)
                    pa += __shfl_xor_sync(FULL, pa, oo);
                if (lane == 0) s_wactm[warp] = pa;
            }
            __syncthreads();
            {   // warps 0-7: ns_w msg rows; warps 8-15: nm_w msg rows
                const float4* g4 = (warp < 8) ? (const float4*)ns_w
                                              : (const float4*)nm_w;
                float* red = (warp < 8) ? sredA : sredB;
                int wl = warp & 7;
                float4 a = make_float4(0.f, 0.f, 0.f, 0.f);
                int kb = wl * 16;
#pragma unroll 8
                for (int kk = 0; kk < 16; kk++) {
                    float  mk = s_msg[kb + kk];
                    float4 w4 = g4[(128 + kb + kk) * 32 + lane];
                    a.x += mk * w4.x; a.y += mk * w4.y;
                    a.z += mk * w4.z; a.w += mk * w4.w;
                }
                ((float4*)red)[wl * 32 + lane] = a;
            }
            __syncthreads();
            if (t < 128) {
                float sa = 0.f, sb = 0.f;
#pragma unroll
                for (int j = 0; j < 8; j++) {
                    sa += sredA[j * 128 + t];
                    sb += sredB[j * 128 + t];
                }
                s_nsmsg[t] = sa; s_nmmsg[t] = sb;
            }
            if (t == 0)
                s_actmsg = s_wactm[0] + s_wactm[1] + s_wactm[2] + s_wactm[3];
            __syncthreads();
            last_mid = mid;
        }

        // ---- gather feats (+ act feats-half partial); warp8: neighbors ----
        int mynb = 0;
        {
            float pa = 0.0f;
            if (t < 128) {
                float xv = g_feats[node * Hh + t];
                xs[t] = xv;
                pa = xv * s_actw[t];
            } else if (warp == 8 && lane < DEGk) {
                mynb = neighbors[node * DEGk + lane];
            }
            if (warp < 4) {
#pragma unroll
                for (int oo = 16; oo; oo >>= 1)
                    pa += __shfl_xor_sync(FULL, pa, oo);
                if (lane == 0) s_wact[warp] = pa;
            }
        }
        __syncthreads();   // sync #1: xs, s_wact ready

        // ---- ACT finalize (all threads, redundantly) ----
        float na;
        {
            float a = s_wact[0] + s_wact[1] + s_wact[2] + s_wact[3]
                    + s_actmsg + actb;
            float cand = 1.0f / (1.0f + expf(-a));
            na = (ta + cand > 1.0f) ? (1.0f - ta) : cand;
        }
        if (t == 0) s_tact[node] = ta + na;

        // ---- ns matvec (register weights, warp-local reduce) ----
        {
            const unsigned long long* xp = (const unsigned long long*)xs;
            unsigned long long acc = 0ull;          // {+0.f, +0.f}
#pragma unroll
            for (int kk = 0; kk < 16; kk++)
                acc = fma2(xp[c * 16 + kk], wA[kk], acc);
            float ax, ay; unpack2(acc, ax, ay);
            ax += __shfl_xor_sync(FULL, ax, 8);
            ay += __shfl_xor_sync(FULL, ay, 8);
            ax += __shfl_xor_sync(FULL, ax, 16);
            ay += __shfl_xor_sync(FULL, ay, 16);
            if (c == 0) {
                float s = ax + ay + s_nsb[o] + s_nsmsg[o];
                float nsv = fmaxf(s, 0.0f);
                ys[o] = nsv;
                g_feats[node * Hh + o]  = nsv;
                g_final[node * Hh + o] += nsv * na;
            }
        }
        __syncthreads();   // sync #2: ys ready

        // ---- nm matvec over ys (register weights) ----
        const int newmid = NSMAX + nproc;
        {
            const unsigned long long* yp = (const unsigned long long*)ys;
            unsigned long long acc = 0ull;
#pragma unroll
            for (int kk = 0; kk < 16; kk++)
                acc = fma2(yp[c * 16 + kk], wB[kk], acc);
            float ax, ay; unpack2(acc, ax, ay);
            ax += __shfl_xor_sync(FULL, ax, 8);
            ay += __shfl_xor_sync(FULL, ay, 8);
            ax += __shfl_xor_sync(FULL, ax, 16);
            ay += __shfl_xor_sync(FULL, ay, 16);
            if (c == 0) {
                float s = ax + ay + s_nmb[o] + s_nmmsg[o];
                g_msgs[(size_t)newmid * Mm + o] = s;   // store message ONCE
            }
        }
        if (warp == 8 && lane < DEGk) {                // enqueue 16 (node,mid)
            int slot = tail + lane;
            if (slot < MAXD) s_qpack[slot] = (newmid << 10) | mynb;
        }

        head = pos + 1;
        tail += DEGk;
        nproc += 1;
        last_mid = mid;
        __syncthreads();   // sync #3: queue/tact/msg visible to next scan
    }
}

// ---------------------------------------------------------------------------
// Kernel 3: readout.  g = sum_n final; logits = g . dec_w + dec_b; log_softmax
// ---------------------------------------------------------------------------
__global__ void k_readout(const float* __restrict__ dec_w,
                          const float* __restrict__ dec_b,
                          float* __restrict__ out)
{
    __shared__ float sg[Hh];
    __shared__ float sl[Pp * OUTn];
    int t = threadIdx.x;

    float acc = 0.0f;
#pragma unroll 4
    for (int n = 0; n < Nn; n++) acc += g_final[n * Hh + t];
    sg[t] = acc;
    __syncthreads();

    if (t < Pp * OUTn) {
        int p = t / OUTn, o = t - p * OUTn;
        float a = dec_b[t];
#pragma unroll 4
        for (int h = 0; h < Hh; h++)
            a += sg[h] * dec_w[(p * Hh + h) * OUTn + o];
        sl[t] = a;
    }
    __syncthreads();

    if (t < Pp) {
        float mx = -1e30f;
        for (int o = 0; o < OUTn; o++) mx = fmaxf(mx, sl[t * OUTn + o]);
        float s = 0.0f;
        for (int o = 0; o < OUTn; o++) s += expf(sl[t * OUTn + o] - mx);
        float lse = mx + logf(s);
        for (int o = 0; o < OUTn; o++)
            out[t * OUTn + o] = sl[t * OUTn + o] - lse;
    }
}

// ---------------------------------------------------------------------------
extern "C" void kernel_launch(void* const* d_in, const int* in_sizes, int n_in,
                              void* d_out, int out_size)
{
    int off = (n_in >= 14) ? 1 : 0;
    const float* xa        = (const float*)d_in[0];
    const float* fmsg      = (const float*)d_in[1];
    const int*   neighbors = (const int*)  d_in[2];
    const int*   nstart    = off ? (const int*)d_in[3] : nullptr;
    const float* enc_w = (const float*)d_in[3 + off];
    const float* enc_b = (const float*)d_in[4 + off];
    const float* ns_w  = (const float*)d_in[5 + off];
    const float* ns_b  = (const float*)d_in[6 + off];
    const float* nm_w  = (const float*)d_in[7 + off];
    const float* nm_b  = (const float*)d_in[8 + off];
    const float* act_w = (const float*)d_in[9 + off];
    const float* act_b = (const float*)d_in[10 + off];
    const float* dec_w = (const float*)d_in[11 + off];
    const float* dec_b = (const float*)d_in[12 + off];

    static const size_t DYN = MAXD * sizeof(int);   // 40 KB packed queue
    cudaFuncSetAttribute(k_main, cudaFuncAttributeMaxDynamicSharedMemorySize,
                         (int)DYN);

    k_init<<<Nn, Hh>>>(xa, fmsg, nstart, enc_w, enc_b);
    k_main<<<1, 512, DYN>>>(neighbors, nstart, ns_w, ns_b, nm_w, nm_b,
                            act_w, act_b);
    k_readout<<<1, Hh>>>(dec_w, dec_b, (float*)d_out);
}

// round 6
// speedup vs baseline: 2.3299x; 1.0792x over previous
#include <cuda_runtime.h>

// Problem constants (fixed by the reference)
#define Nn    1000
#define INF_  32
#define Hh    128
#define Mm    128
#define DEGk  16
#define Pp    2
#define OUTn  10
#define MAXD  (10 * Nn)                 // dequeue budget = queue slots ever read
#define NSMAX 64
#define MAXMSG (NSMAX + MAXD)           // distinct messages ever created
#define THR   (1.0f - 1e-7f)

// Persistent device state (static allocation — no cudaMalloc allowed)
__device__ float g_feats[Nn * Hh];
__device__ float g_final[Nn * Hh];
__device__ float g_actf[Nn];
__device__ float g_msgs[(size_t)MAXMSG * Mm];   // dedup'd message store (~5.2 MB)

// ---- packed f32x2 helpers (sm_103a) ---------------------------------------
__device__ __forceinline__ unsigned long long fma2(unsigned long long a,
                                                   unsigned long long b,
                                                   unsigned long long c)
{
    unsigned long long d;
    asm("fma.rn.f32x2 %0, %1, %2, %3;" : "=l"(d) : "l"(a), "l"(b), "l"(c));
    return d;
}
__device__ __forceinline__ unsigned long long pack2(float lo, float hi)
{
    unsigned long long d;
    asm("mov.b64 %0, {%1, %2};" : "=l"(d) : "f"(lo), "f"(hi));
    return d;
}
__device__ __forceinline__ void unpack2(unsigned long long v, float& lo, float& hi)
{
    asm("mov.b64 {%0, %1}, %2;" : "=f"(lo), "=f"(hi) : "l"(v));
}

// ---------------------------------------------------------------------------
// Kernel 1: encoder + state init + seed messages + actf seed. grid = Nn x 128
// ---------------------------------------------------------------------------
__global__ void k_init(const float* __restrict__ xa,
                       const float* __restrict__ fmsg,
                       const int*  nstart_p,
                       const float* __restrict__ enc_w,
                       const float* __restrict__ enc_b,
                       const float* __restrict__ act_w)
{
    int n = blockIdx.x, t = threadIdx.x;
    int lane = t & 31;
    __shared__ float sx[INF_];
    __shared__ float sw[4];
    if (t < INF_) sx[t] = xa[n * INF_ + t];
    __syncthreads();

    float acc = enc_b[t];
#pragma unroll
    for (int k = 0; k < INF_; k++) acc += sx[k] * enc_w[k * Hh + t];

    g_feats[n * Hh + t] = acc;
    g_final[n * Hh + t] = 0.0f;

    // actf seed: enc_out . act_w[0:128]
    float pa = acc * act_w[t];
#pragma unroll
    for (int o = 16; o; o >>= 1) pa += __shfl_xor_sync(0xffffffffu, pa, o);
    if (lane == 0) sw[t >> 5] = pa;
    __syncthreads();
    if (t == 0) g_actf[n] = sw[0] + sw[1] + sw[2] + sw[3];

    int ns = nstart_p ? *nstart_p : NSMAX;
    if (n < ns) g_msgs[(size_t)n * Mm + t] = fmsg[n * Mm + t];
}

// ---- warp-uniform ballot skip-scan over SMEM queue ------------------------
__device__ __forceinline__ void scan_q(const int* __restrict__ s_qpack,
                                       const float* __restrict__ s_tact,
                                       int p_start, int limit, int lane,
                                       int& found, int& fpos, int& fpk, float& fta)
{
    const unsigned FULL = 0xffffffffu;
    int p = p_start + lane;
    found = 0; fpos = 0; fpk = 0; fta = 0.0f;
    while (true) {
        bool  valid = (p < limit);
        int   pk    = valid ? s_qpack[p] : 0;
        float tv    = valid ? s_tact[pk & 1023] : 2.0f;
        unsigned ok = __ballot_sync(FULL, valid && (tv <= THR));
        if (ok) {
            int f = __ffs((int)ok) - 1;
            fpos  = (p - lane) + f;
            fpk   = __shfl_sync(FULL, pk, f);
            fta   = __shfl_sync(FULL, tv, f);
            found = 1;
            return;
        }
        if (__ballot_sync(FULL, valid) != FULL) return;
        p += 32;
    }
}

// ---------------------------------------------------------------------------
// Kernel 2: sequential queue simulation. ONE block, 512 threads (16 warps).
//  * queue + tact + actf caches in SMEM; msg-half weights in SMEM
//  * hit-path weights register-resident (fma.rn.f32x2), warp-local reduce
//  * next-entry speculation: prefetch feats/final/msg rows one step ahead
//  * ACT gate from cached per-node / per-mid dot products (no block reduce)
//  * 2 barriers per hit step
// ---------------------------------------------------------------------------
__global__ void __launch_bounds__(512, 1) k_main(
    const int*  __restrict__ neighbors,
    const int*  nstart_p,
    const float* __restrict__ ns_w, const float* __restrict__ ns_b,
    const float* __restrict__ nm_w, const float* __restrict__ nm_b,
    const float* __restrict__ act_w, const float* __restrict__ act_b)
{
    extern __shared__ __align__(16) float dyn[];
    float* s_mwA  = dyn;                      // ns_w rows 128..255 (64 KB)
    float* s_mwB  = dyn + 128 * 128;          // nm_w rows 128..255 (64 KB)
    int*   s_qpack = (int*)(dyn + 2 * 128 * 128);   // packed queue (40 KB)

    __shared__ float s_tact[Nn];                    // 4 KB
    __shared__ float s_actf[Nn];                    // 4 KB
    __shared__ __align__(16) float xs[128];         // feats[node] (prefetched)
    __shared__ __align__(16) float ys[128];         // ns output (relu)
    __shared__ __align__(16) float s_fin[128];      // g_final[node] (prefetched)
    __shared__ float s_msg[128];
    __shared__ float s_nsmsg[128], s_nmmsg[128];    // cached msg-half partials
    __shared__ __align__(16) float sredA[8 * 128];
    __shared__ __align__(16) float sredB[8 * 128];
    __shared__ float s_actw[256];
    __shared__ float s_nsb[128], s_nmb[128];
    __shared__ float s_wtmp[16];                    // per-warp actf partials
    __shared__ float s_wactm[4];
    __shared__ float s_actmsg;
    __shared__ int   s_next[4];                     // {pos, pk, ta_bits, found}

    const int t    = threadIdx.x;
    const int lane = t & 31;
    const int warp = t >> 5;
    const unsigned FULL = 0xffffffffu;

    if (t < 256) s_actw[t] = act_w[t];
    if (t < 128) { s_nsb[t] = ns_b[t]; s_nmb[t] = nm_b[t]; }
    if (t < 16)  s_wtmp[t] = 0.0f;
    if (t == 0)  s_actmsg = 0.0f;
    const float actb = act_b[0];

    for (int i = t; i < Nn; i += 512) { s_tact[i] = 0.0f; s_actf[i] = g_actf[i]; }

    const int ns0 = nstart_p ? *nstart_p : NSMAX;
    for (int i = t; i < ns0; i += 512) s_qpack[i] = (i << 10) | i;  // mid=i,node=i

    // msg-half weights into SMEM (rows 128..255 of both matrices)
    {
        const float4* a4 = (const float4*)(ns_w + 128 * Hh);
        const float4* b4 = (const float4*)(nm_w + 128 * Hh);
        for (int i = t; i < 128 * 32; i += 512) {
            ((float4*)s_mwA)[i] = a4[i];
            ((float4*)s_mwB)[i] = b4[i];
        }
    }

    // hit-path weights into registers (k-pair packed)
    const int o = (warp << 3) + (lane & 7);     // output column owned
    const int c = lane >> 3;                    // k-chunk (0..3)
    unsigned long long wA[16], wB[16];
#pragma unroll
    for (int kk = 0; kk < 16; kk++) {
        int k = c * 32 + 2 * kk;
        wA[kk] = pack2(ns_w[k * Hh + o], ns_w[(k + 1) * Hh + o]);
        wB[kk] = pack2(nm_w[k * Hh + o], nm_w[(k + 1) * Hh + o]);
    }

    int head = 0, tail = ns0, nproc = 0;
    int last_mid = -1, node_prev = -1;
    int have = 0, pos = 0, pk = 0; float ta = 0.0f;
    __syncthreads();

    while (true) {
        const int limit = (tail < MAXD) ? tail : MAXD;

        if (!have) {
            if (head >= limit) break;
            int f, fp, fk; float ft;
            scan_q(s_qpack, s_tact, head, limit, lane, f, fp, fk, ft);
            if (!f) break;
            pos = fp; pk = fk; ta = ft;
            int cn = pk & 1023, cm = pk >> 10;
            if (t < 128) {
                xs[t]    = g_feats[cn * Hh + t];
                s_fin[t] = g_final[cn * Hh + t];
                if (cm != last_mid) s_msg[t] = g_msgs[(size_t)cm * Mm + t];
            }
            __syncthreads();
            have = 1;
        }

        const int node = pk & 1023;
        const int mid  = pk >> 10;

        // neighbors LDG early (warp 4) — consumed in phase 3
        int mynb = 0;
        if (warp == 4 && lane < DEGk) mynb = neighbors[node * DEGk + lane];

        // ---- miss path: msg-half partials for this mid (SMEM weights) ----
        if (mid != last_mid) {
            if (warp < 4) {                       // act msg-half partial
                float pa = s_msg[t] * s_actw[128 + t];
#pragma unroll
                for (int oo = 16; oo; oo >>= 1)
                    pa += __shfl_xor_sync(FULL, pa, oo);
                if (lane == 0) s_wactm[warp] = pa;
            }
            {
                const float4* w4p = (warp < 8) ? (const float4*)s_mwA
                                               : (const float4*)s_mwB;
                float* red = (warp < 8) ? sredA : sredB;
                int wl = warp & 7, kb = (warp & 7) * 16;
                float4 a = make_float4(0.f, 0.f, 0.f, 0.f);
#pragma unroll 8
                for (int kk = 0; kk < 16; kk++) {
                    float  mk = s_msg[kb + kk];
                    float4 w4 = w4p[(kb + kk) * 32 + lane];
                    a.x += mk * w4.x; a.y += mk * w4.y;
                    a.z += mk * w4.z; a.w += mk * w4.w;
                }
                ((float4*)red)[wl * 32 + lane] = a;
            }
            __syncthreads();
            if (t < 128) {
                float sa = 0.f, sb = 0.f;
#pragma unroll
                for (int j = 0; j < 8; j++) {
                    sa += sredA[j * 128 + t];
                    sb += sredB[j * 128 + t];
                }
                s_nsmsg[t] = sa; s_nmmsg[t] = sb;
            }
            if (t == 0)
                s_actmsg = s_wactm[0] + s_wactm[1] + s_wactm[2] + s_wactm[3];
            __syncthreads();
            last_mid = mid;
        }

        // ---- ACT gate (all threads, cached dots; no block reduce) ----
        float wsum = 0.0f;
#pragma unroll
        for (int j = 0; j < 16; j++) wsum += s_wtmp[j];
        float actf = (node == node_prev) ? wsum : s_actf[node];
        if (t == 0 && node_prev >= 0) s_actf[node_prev] = wsum;

        float na;
        {
            float a = actf + s_actmsg + actb;
            float cand = 1.0f / (1.0f + expf(-a));
            na = (ta + cand > 1.0f) ? (1.0f - ta) : cand;
        }
        if (t == 0) s_tact[node] = ta + na;

        // ---- speculation for next entry: issue prefetch LDGs now ----
        const int np = pos + 1;
        int spec = 0, spack = 0; float stv = 0.0f;
        float xpre = 0.f, fpre = 0.f, mpre = 0.f;
        if (t < 128 && np < limit) {
            spack = s_qpack[np];
            int snode = spack & 1023;
            stv = (snode == node) ? (ta + na) : s_tact[snode];
            if (stv <= THR) {
                spec = 1;
                xpre = g_feats[snode * Hh + t];
                fpre = g_final[snode * Hh + t];
                int smid = spack >> 10;
                if (smid != mid) mpre = g_msgs[(size_t)smid * Mm + t];
            }
        }

        // ---- phase 2: ns matvec (register weights) ----
        {
            const unsigned long long* xp = (const unsigned long long*)xs;
            unsigned long long a0 = 0ull, a1 = 0ull;
#pragma unroll
            for (int kk = 0; kk < 8; kk++) {
                a0 = fma2(xp[c * 16 + 2 * kk],     wA[2 * kk],     a0);
                a1 = fma2(xp[c * 16 + 2 * kk + 1], wA[2 * kk + 1], a1);
            }
            float ax, ay, bx, by;
            unpack2(a0, ax, ay); unpack2(a1, bx, by);
            ax += bx; ay += by;
            ax += __shfl_xor_sync(FULL, ax, 8);
            ay += __shfl_xor_sync(FULL, ay, 8);
            ax += __shfl_xor_sync(FULL, ax, 16);
            ay += __shfl_xor_sync(FULL, ay, 16);
            if (c == 0) {
                float s = ax + ay + s_nsb[o] + s_nsmsg[o];
                float nsv = fmaxf(s, 0.0f);
                ys[o] = nsv;
                g_feats[node * Hh + o] = nsv;
                g_final[node * Hh + o] = s_fin[o] + nsv * na;
                // actf partial for this node (8 lanes -> lane0)
                float pw = nsv * s_actw[o];
                pw += __shfl_xor_sync(0x000000ffu, pw, 4);
                pw += __shfl_xor_sync(0x000000ffu, pw, 2);
                pw += __shfl_xor_sync(0x000000ffu, pw, 1);
                if (lane == 0) s_wtmp[warp] = pw;
            }
        }
        __syncthreads();   // sync2: ys ready; tact/feats/final stores visible

        // ---- phase 3: nm matvec + roles ----
        const int newmid = NSMAX + nproc;
        {
            const unsigned long long* yp = (const unsigned long long*)ys;
            unsigned long long a0 = 0ull, a1 = 0ull;
#pragma unroll
            for (int kk = 0; kk < 8; kk++) {
                a0 = fma2(yp[c * 16 + 2 * kk],     wB[2 * kk],     a0);
                a1 = fma2(yp[c * 16 + 2 * kk + 1], wB[2 * kk + 1], a1);
            }
            float ax, ay, bx, by;
            unpack2(a0, ax, ay); unpack2(a1, bx, by);
            ax += bx; ay += by;
            ax += __shfl_xor_sync(FULL, ax, 8);
            ay += __shfl_xor_sync(FULL, ay, 8);
            ax += __shfl_xor_sync(FULL, ax, 16);
            ay += __shfl_xor_sync(FULL, ay, 16);
            if (c == 0) {
                float s = ax + ay + s_nmb[o] + s_nmmsg[o];
                g_msgs[(size_t)newmid * Mm + o] = s;   // store message ONCE
            }
        }
        if (warp == 4 && lane < DEGk) {                // enqueue 16 entries
            int slot = tail + lane;
            if (slot < MAXD) s_qpack[slot] = (newmid << 10) | mynb;
        }
        if (warp < 4) {                                // next-entry finalize
            int f, fp, fk; float ft;
            if (spec) { f = 1; fp = np; fk = spack; ft = stv; }
            else      scan_q(s_qpack, s_tact, np, limit, lane, f, fp, fk, ft);
            if (f) {
                int nnode = fk & 1023, nmid = fk >> 10;
                xs[t]    = spec ? xpre : g_feats[nnode * Hh + t];
                s_fin[t] = spec ? fpre : g_final[nnode * Hh + t];
                if (nmid != mid)
                    s_msg[t] = spec ? mpre : g_msgs[(size_t)nmid * Mm + t];
            }
            if (t == 0) {
                s_next[0] = fp; s_next[1] = fk;
                s_next[2] = __float_as_int(ft); s_next[3] = f;
            }
        }

        node_prev = node;
        head = np;
        tail += DEGk;
        nproc += 1;
        __syncthreads();   // sync3: everything visible; s_next ready

        pos = s_next[0]; pk = s_next[1];
        ta  = __int_as_float(s_next[2]);
        have = s_next[3];
    }
}

// ---------------------------------------------------------------------------
// Kernel 3: readout.  g = sum_n final; logits = g . dec_w + dec_b; log_softmax
// ---------------------------------------------------------------------------
__global__ void k_readout(const float* __restrict__ dec_w,
                          const float* __restrict__ dec_b,
                          float* __restrict__ out)
{
    __shared__ float sg[Hh];
    __shared__ float sl[Pp * OUTn];
    int t = threadIdx.x;

    float acc = 0.0f;
#pragma unroll 4
    for (int n = 0; n < Nn; n++) acc += g_final[n * Hh + t];
    sg[t] = acc;
    __syncthreads();

    if (t < Pp * OUTn) {
        int p = t / OUTn, o = t - p * OUTn;
        float a = dec_b[t];
#pragma unroll 4
        for (int h = 0; h < Hh; h++)
            a += sg[h] * dec_w[(p * Hh + h) * OUTn + o];
        sl[t] = a;
    }
    __syncthreads();

    if (t < Pp) {
        float mx = -1e30f;
        for (int o = 0; o < OUTn; o++) mx = fmaxf(mx, sl[t * OUTn + o]);
        float s = 0.0f;
        for (int o = 0; o < OUTn; o++) s += expf(sl[t * OUTn + o] - mx);
        float lse = mx + logf(s);
        for (int o = 0; o < OUTn; o++)
            out[t * OUTn + o] = sl[t * OUTn + o] - lse;
    }
}

// ---------------------------------------------------------------------------
extern "C" void kernel_launch(void* const* d_in, const int* in_sizes, int n_in,
                              void* d_out, int out_size)
{
    int off = (n_in >= 14) ? 1 : 0;
    const float* xa        = (const float*)d_in[0];
    const float* fmsg      = (const float*)d_in[1];
    const int*   neighbors = (const int*)  d_in[2];
    const int*   nstart    = off ? (const int*)d_in[3] : nullptr;
    const float* enc_w = (const float*)d_in[3 + off];
    const float* enc_b = (const float*)d_in[4 + off];
    const float* ns_w  = (const float*)d_in[5 + off];
    const float* ns_b  = (const float*)d_in[6 + off];
    const float* nm_w  = (const float*)d_in[7 + off];
    const float* nm_b  = (const float*)d_in[8 + off];
    const float* act_w = (const float*)d_in[9 + off];
    const float* act_b = (const float*)d_in[10 + off];
    const float* dec_w = (const float*)d_in[11 + off];
    const float* dec_b = (const float*)d_in[12 + off];

    // dyn smem: 128 KB msg-half weights + 40 KB packed queue
    static const size_t DYN = 2 * 128 * 128 * sizeof(float) + MAXD * sizeof(int);
    cudaFuncSetAttribute(k_main, cudaFuncAttributeMaxDynamicSharedMemorySize,
                         (int)DYN);

    k_init<<<Nn, Hh>>>(xa, fmsg, nstart, enc_w, enc_b, act_w);
    k_main<<<1, 512, DYN>>>(neighbors, nstart, ns_w, ns_b, nm_w, nm_b,
                            act_w, act_b);
    k_readout<<<1, Hh>>>(dec_w, dec_b, (float*)d_out);
}